// round 14
// baseline (speedup 1.0000x reference)
#include <cuda_runtime.h>
#include <math.h>

#define BATCH 64
#define SEQ   512
#define EMB   512
#define HID   1024
#define BH    (BATCH * HID)        // 65536
#define SBH   (SEQ * BH)           // 33554432
#define KSLICES 8
#define NBLOCKS 128                // 16 h-tiles (64h) x 8 k-slices (128k)

// smem: Ws[128][64] (32 KB) + 8 warp-private As[128][8] (32 KB)
#define RNN_SMEM ((128 * 64 + 8 * 128 * 8) * 4)
#define XPSZ (KSLICES * BH)        // one parity of xproj partials

typedef unsigned long long u64;

// W_aa K-split partials: [KSLICES][BATCH][HID] = 2 MB
__device__ float g_partial[KSLICES * BH];
// xproj E-split partials, parity-double-buffered: [2][KSLICES][BATCH][HID] = 4 MB
__device__ float g_xpbuf[2 * XPSZ];
// Counters: ca @ 0, cp @ 2048, cx @ 4096 — each [(g*8+w)*16]
__device__ unsigned g_sync[8192];

// ---------------- packed fp32x2 helpers (sm_103a) ---------------------------
__device__ __forceinline__ u64 pkdup(float x) {
    u64 r; asm("mov.b64 %0, {%1, %1};" : "=l"(r) : "f"(x)); return r;
}
__device__ __forceinline__ void fma2(u64& d, u64 a, u64 b) {
    asm("fma.rn.f32x2 %0, %1, %2, %0;" : "+l"(d) : "l"(a), "l"(b));
}
__device__ __forceinline__ float2 un2(u64 v) {
    float2 f; asm("mov.b64 {%0, %1}, %2;" : "=f"(f.x), "=f"(f.y) : "l"(v));
    return f;
}
__device__ __forceinline__ unsigned ldacq(const unsigned* p) {
    unsigned v;
    asm volatile("ld.acquire.gpu.global.u32 %0, [%1];" : "=r"(v) : "l"(p));
    return v;
}
__device__ __forceinline__ void redrel(unsigned* p) {
    asm volatile("red.release.gpu.global.add.u32 [%0], %1;"
                 :: "l"(p), "r"(1u) : "memory");
}

// ---------------------------------------------------------------------------
// xproj front (per warp): partial[b 8w..8w+8)[h0+hh, +1] over e-slice
// [64ks, 64ks+64) of   sum_e X[b][st][e] * Wax[h][e],  written to gp.
// Uses the warp-private Asw buffer (caller guarantees it is free).
// ---------------------------------------------------------------------------
__device__ __forceinline__ void xproj_front(
    const float* __restrict__ X, const float* __restrict__ wx0,
    const float* __restrict__ wx1, float* Asw, float* gp,
    int st, int e0, int w, int l)
{
    const int sbp = l & 7;
    const int seb = (l >> 3) * 16;

    // stage X[8w+sbp][st][e0+seb .. +16) into e-major Asw[e][8]
    const float* xsrc = X + ((size_t)(8 * w + sbp) * SEQ + st) * EMB + e0 + seb;
    float4 t4[4];
#pragma unroll
    for (int j = 0; j < 4; j++)
        t4[j] = __ldcg((const float4*)(xsrc + j * 4));
#pragma unroll
    for (int j = 0; j < 4; j++) {
        int e = seb + j * 4;
        Asw[(e + 0) * 8 + sbp] = t4[j].x;
        Asw[(e + 1) * 8 + sbp] = t4[j].y;
        Asw[(e + 2) * 8 + sbp] = t4[j].z;
        Asw[(e + 3) * 8 + sbp] = t4[j].w;
    }
    __syncwarp();

    u64 acc[4][2];
#pragma unroll
    for (int i = 0; i < 4; i++) { acc[i][0] = 0ull; acc[i][1] = 0ull; }

#pragma unroll 4
    for (int eb = 0; eb < 64; eb += 4) {
        float4 wr0 = __ldcg((const float4*)(wx0 + e0 + eb));
        float4 wr1 = __ldcg((const float4*)(wx1 + e0 + eb));
        float wa[4] = {wr0.x, wr0.y, wr0.z, wr0.w};
        float wb[4] = {wr1.x, wr1.y, wr1.z, wr1.w};
#pragma unroll
        for (int u = 0; u < 4; u++) {
            ulonglong2 aA = *(const ulonglong2*)(Asw + (eb + u) * 8);
            ulonglong2 aB = *(const ulonglong2*)(Asw + (eb + u) * 8 + 4);
            u64 q0 = pkdup(wa[u]);
            u64 q1 = pkdup(wb[u]);
            fma2(acc[0][0], aA.x, q0); fma2(acc[0][1], aA.x, q1);
            fma2(acc[1][0], aA.y, q0); fma2(acc[1][1], aA.y, q1);
            fma2(acc[2][0], aB.x, q0); fma2(acc[2][1], aB.x, q1);
            fma2(acc[3][0], aB.y, q0); fma2(acc[3][1], aB.y, q1);
        }
    }

#pragma unroll
    for (int bp = 0; bp < 4; bp++) {
        float2 ev = un2(acc[bp][0]);
        float2 ov = un2(acc[bp][1]);
        *(float2*)(gp + (size_t)(2 * bp)     * HID) = make_float2(ev.x, ov.x);
        *(float2*)(gp + (size_t)(2 * bp + 1) * HID) = make_float2(ev.y, ov.y);
    }
}

// ---------------------------------------------------------------------------
// Persistent fused kernel (R11 scan structure + xproj folded into bubbles).
// CTA bi: h-tile ht=bi>>3 (64 h), k-slice ks=bi&7 (128 k / 64 e), g=ht>>1.
// Warp w owns batch-group w. Per step s>=1:
//   wait ca[ks][w]>=16s & ca[g][w]>=16s; stage a_{s-1}; compute waa partials;
//   STG; rel cp[g][w];   xproj(s+1) partials -> xpbuf[(s+1)&1]; rel cx[g][w];
//   wait cp>=16s & cx>=16s; phase2: tanh(bias + sum8 xp + sum8 waa); rel ca.
// Prologue computes xproj(0) and xproj(1); phase2(0) uses xp only.
// ---------------------------------------------------------------------------
__global__ __launch_bounds__(256) void rnn_persistent(
    const float* __restrict__ Waa, const float* __restrict__ Wax,
    const float* __restrict__ X, const float* __restrict__ ba,
    float* __restrict__ outs, int write_hidden)
{
    extern __shared__ float sm[];
    float* Ws = sm;                           // [128][64]

    const int tid = threadIdx.x;
    const int bi  = blockIdx.x;
    const int ht  = bi >> 3;                  // 0..15
    const int ks  = bi & 7;                   // 0..7
    const int g   = ht >> 1;                  // 0..7
    const int h0  = ht * 64;
    const int k0  = ks * 128;
    const int e0  = ks * 64;                  // xproj e-slice
    const int w   = tid >> 5;                 // warp = batch-group 0..7
    const int l   = tid & 31;

    float* Asw = sm + 128 * 64 + w * (128 * 8);   // private [128][8]

    unsigned* ca_own = g_sync + (g * 8 + w) * 16;
    unsigned* ca_ks  = g_sync + (ks * 8 + w) * 16;
    unsigned* cp_own = g_sync + 2048 + (g * 8 + w) * 16;
    unsigned* cx_own = g_sync + 4096 + (g * 8 + w) * 16;

    // Load W_aa slice once: Ws[k][h] = Waa[h0+h][k0+k]
    {
        const int h  = tid & 63;
        const int kg = tid >> 6;
        const float* wrow = Waa + (size_t)(h0 + h) * HID + k0 + kg * 32;
#pragma unroll
        for (int j = 0; j < 8; j++) {
            float4 wv = *(const float4*)(wrow + j * 4);
            int k = kg * 32 + j * 4;
            Ws[(k + 0) * 64 + h] = wv.x; Ws[(k + 1) * 64 + h] = wv.y;
            Ws[(k + 2) * 64 + h] = wv.z; Ws[(k + 3) * 64 + h] = wv.w;
        }
    }
    __syncthreads();

    const int hh = 2 * l;                     // h-pair within 64
    const int sbp = l & 7;                    // staging b
    const int skb = (l >> 3) * 4;             // staging k base
    // phase2 map: element (b = 8w + (cg>>1), h = 128g + (cg&1)*64 + hh)
    const int cg  = ((ht & 1) << 3) | ks;
    const size_t p2off = (size_t)(8 * w + (cg >> 1)) * HID
                       + (size_t)g * 128 + (cg & 1) * 64 + hh;

    const float* wx0 = Wax + (size_t)(h0 + hh) * EMB;
    const float* wx1 = wx0 + EMB;
    const float2 bias = *(const float2*)(ba + g * 128 + ((cg & 1) << 6) + hh);

    // xproj partial destination (fixed except parity)
    float* xgp = g_xpbuf + (size_t)ks * BH + (size_t)(8 * w) * HID + h0 + hh;

    // ---- prologue: xproj(0) -> buf0, xproj(1) -> buf1
    xproj_front(X, wx0, wx1, Asw, xgp,            0, e0, w, l);
    __syncwarp();
    xproj_front(X, wx0, wx1, Asw, xgp + XPSZ,     1, e0, w, l);
    __syncwarp();
    if (l == 0) redrel(cx_own);               // cx = 16 (covers s=0 and s=1)

    for (int s = 0; s < SEQ; s++) {
        const unsigned t = 16u * (unsigned)s;

        if (s > 0) {
            if (l == 0) {
                while (ldacq(ca_ks) < t) { }
                if (ca_own != ca_ks) while (ldacq(ca_own) < t) { }
            }
            __syncwarp();

            // ---- stage a_{s-1}[8 rows][128 k] into private k-major smem
            const float* src = outs + (size_t)(s - 1) * BH
                             + (size_t)(8 * w + sbp) * HID + k0 + skb;
#pragma unroll
            for (int j = 0; j < 8; j++) {
                float4 v = __ldcg((const float4*)(src + j * 16));
                int k = skb + j * 16;
                Asw[(k + 0) * 8 + sbp] = v.x;
                Asw[(k + 1) * 8 + sbp] = v.y;
                Asw[(k + 2) * 8 + sbp] = v.z;
                Asw[(k + 3) * 8 + sbp] = v.w;
            }
            __syncwarp();

            // ---- compute waa partials acc[4 b-pairs][2 h] over 128 k
            u64 acc[4][2];
#pragma unroll
            for (int i = 0; i < 4; i++) { acc[i][0] = 0ull; acc[i][1] = 0ull; }

#pragma unroll 8
            for (int k = 0; k < 128; k++) {
                ulonglong2 aA = *(const ulonglong2*)(Asw + k * 8);
                ulonglong2 aB = *(const ulonglong2*)(Asw + k * 8 + 4);
                float2 wv = *(const float2*)(Ws + k * 64 + hh);
                u64 w0 = pkdup(wv.x);
                u64 w1 = pkdup(wv.y);
                fma2(acc[0][0], aA.x, w0); fma2(acc[0][1], aA.x, w1);
                fma2(acc[1][0], aA.y, w0); fma2(acc[1][1], aA.y, w1);
                fma2(acc[2][0], aB.x, w0); fma2(acc[2][1], aB.x, w1);
                fma2(acc[3][0], aB.y, w0); fma2(acc[3][1], aB.y, w1);
            }

            // ---- write waa partials
            float* gp = g_partial + (size_t)ks * BH
                      + (size_t)(8 * w) * HID + h0 + hh;
#pragma unroll
            for (int bp = 0; bp < 4; bp++) {
                float2 ev = un2(acc[bp][0]);
                float2 ov = un2(acc[bp][1]);
                *(float2*)(gp + (size_t)(2 * bp)     * HID) = make_float2(ev.x, ov.x);
                *(float2*)(gp + (size_t)(2 * bp + 1) * HID) = make_float2(ev.y, ov.y);
            }
            __syncwarp();
            if (l == 0) redrel(cp_own);

            // ---- xproj(s+1) in the cp-wait bubble (off critical path)
            if (s + 1 < SEQ) {
                xproj_front(X, wx0, wx1, Asw, xgp + (size_t)((s + 1) & 1) * XPSZ,
                            s + 1, e0, w, l);
                __syncwarp();
                if (l == 0) redrel(cx_own);
            }

            if (l == 0) {
                while (ldacq(cp_own) < t) { }
                while (ldacq(cx_own) < t) { }
            }
            __syncwarp();
        } else {
            if (l == 0) { while (ldacq(cx_own) < 16u) { } }
            __syncwarp();
        }

        // ---- phase2: tanh(bias + sum xp partials + sum waa partials)
        {
            float2 v = bias;
            const float* xpp = g_xpbuf + (size_t)(s & 1) * XPSZ + p2off;
#pragma unroll
            for (int p = 0; p < KSLICES; p++) {
                float2 q = __ldcg((const float2*)(xpp + (size_t)p * BH));
                v.x += q.x; v.y += q.y;
            }
            if (s > 0) {
                const float* pp = g_partial + p2off;
#pragma unroll
                for (int p = 0; p < KSLICES; p++) {
                    float2 q = __ldcg((const float2*)(pp + (size_t)p * BH));
                    v.x += q.x; v.y += q.y;
                }
            }
            v.x = tanhf(v.x); v.y = tanhf(v.y);
            *(float2*)(outs + (size_t)s * BH + p2off) = v;
            if (write_hidden && s == SEQ - 1)
                *(float2*)(outs + (size_t)SBH + p2off) = v;
        }
        __syncwarp();
        if (l == 0) redrel(ca_own);
    }
}

// ---------------------------------------------------------------------------
// Launch. Inputs: X [B,S,E] f32, W_ax [H,E] f32, W_aa [H,H] f32, b_a [H] f32.
// Output: outputs [S,B,H] then hidden [B,H]. Single persistent kernel.
// ---------------------------------------------------------------------------
extern "C" void kernel_launch(void* const* d_in, const int* in_sizes, int n_in,
                              void* d_out, int out_size) {
    (void)in_sizes; (void)n_in;
    const float* X   = (const float*)d_in[0];
    const float* Wax = (const float*)d_in[1];
    const float* Waa = (const float*)d_in[2];
    const float* ba  = (const float*)d_in[3];
    float* out = (float*)d_out;

    cudaFuncSetAttribute(rnn_persistent,
                         cudaFuncAttributeMaxDynamicSharedMemorySize, RNN_SMEM);

    void* sp = nullptr;
    cudaGetSymbolAddress(&sp, g_sync);
    cudaMemsetAsync(sp, 0, 8192 * sizeof(unsigned), 0);

    int write_hidden = (out_size >= (int)(SBH + BH)) ? 1 : 0;
    rnn_persistent<<<NBLOCKS, 256, RNN_SMEM>>>(Waa, Wax, X, ba, out, write_hidden);
}

// round 15
// speedup vs baseline: 1.7279x; 1.7279x over previous
#include <cuda_runtime.h>
#include <math.h>

#define BATCH 64
#define SEQ   512
#define EMB   512
#define HID   1024
#define BH    (BATCH * HID)        // 65536
#define SBH   (SEQ * BH)           // 33554432
#define KSLICES 8
#define NBLOCKS 128                // 16 h-tiles (64h) x 8 k-slices (128k)

#define ASTRIDE 12                 // padded k-major row (floats), 48B = 16B-aligned
#define RNN_SMEM ((128 * 64 + 8 * 128 * ASTRIDE) * 4)   // 32KB Ws + 48KB Asw = 80KB

typedef unsigned long long u64;

// xproj results for all steps: [SEQ][BATCH][HID] = 128 MB (read-only in scan)
__device__ float g_xp[SBH];
// W_aa K-split partials, TRIPLE buffered: [3][KSLICES][BATCH][HID] = 6 MB
__device__ float g_partial[3][KSLICES * BH];
// Counters: cp[g] at g*64, cd[g] at 512+g*64 (monotone, += 16 per step)
__device__ unsigned g_sync[1024];

// ---------------- packed fp32x2 helpers (sm_103a) ---------------------------
__device__ __forceinline__ u64 pkdup(float x) {
    u64 r; asm("mov.b64 %0, {%1, %1};" : "=l"(r) : "f"(x)); return r;
}
__device__ __forceinline__ void fma2(u64& d, u64 a, u64 b) {
    asm("fma.rn.f32x2 %0, %1, %2, %0;" : "+l"(d) : "l"(a), "l"(b));
}
__device__ __forceinline__ float2 un2(u64 v) {
    float2 f; asm("mov.b64 {%0, %1}, %2;" : "=f"(f.x), "=f"(f.y) : "l"(v));
    return f;
}
__device__ __forceinline__ unsigned ldacq(const unsigned* p) {
    unsigned v;
    asm volatile("ld.acquire.gpu.global.u32 %0, [%1];" : "=r"(v) : "l"(p));
    return v;
}
__device__ __forceinline__ void redrel(unsigned* p) {
    asm volatile("red.release.gpu.global.add.u32 [%0], %1;"
                 :: "l"(p), "r"(1u) : "memory");
}

// ---------------------------------------------------------------------------
// Kernel 1: g_xp[s][b][h] = sum_e X[b][s][e] * Wax[h][e] + ba[h]
// (R11's proven xproj GEMM, target = g_xp instead of outs)
// ---------------------------------------------------------------------------
__global__ __launch_bounds__(256) void xproj_kernel(
    const float* __restrict__ X, const float* __restrict__ Wax,
    const float* __restrict__ ba)
{
    __shared__ float As[16][128];
    __shared__ float Bs[16][128];

    const int tid = threadIdx.x;
    const int r0 = blockIdx.x * 128;
    const int h0 = blockIdx.y * 128;

    const int lr = tid >> 1;
    const int lk = (tid & 1) * 8;
    const int r  = r0 + lr;
    const float* Aptr = X + (size_t)(r & (BATCH - 1)) * (SEQ * EMB)
                          + (size_t)(r >> 6) * EMB + lk;
    const float* Bptr = Wax + (size_t)(h0 + lr) * EMB + lk;

    const int tm0 = (tid >> 4) * 4;
    const int tn0 = (tid & 15) * 4;

    u64 acc[8][4];
#pragma unroll
    for (int i = 0; i < 8; i++)
#pragma unroll
        for (int p = 0; p < 4; p++) acc[i][p] = 0ull;

    for (int k0 = 0; k0 < EMB; k0 += 16) {
        float4 a0 = *(const float4*)(Aptr + k0);
        float4 a1 = *(const float4*)(Aptr + k0 + 4);
        float4 b0 = *(const float4*)(Bptr + k0);
        float4 b1 = *(const float4*)(Bptr + k0 + 4);
        As[lk + 0][lr] = a0.x; As[lk + 1][lr] = a0.y;
        As[lk + 2][lr] = a0.z; As[lk + 3][lr] = a0.w;
        As[lk + 4][lr] = a1.x; As[lk + 5][lr] = a1.y;
        As[lk + 6][lr] = a1.z; As[lk + 7][lr] = a1.w;
        Bs[lk + 0][lr] = b0.x; Bs[lk + 1][lr] = b0.y;
        Bs[lk + 2][lr] = b0.z; Bs[lk + 3][lr] = b0.w;
        Bs[lk + 4][lr] = b1.x; Bs[lk + 5][lr] = b1.y;
        Bs[lk + 6][lr] = b1.z; Bs[lk + 7][lr] = b1.w;
        __syncthreads();

#pragma unroll
        for (int k = 0; k < 16; k++) {
            float4 av0 = *(const float4*)&As[k][tm0];
            float4 av1 = *(const float4*)&As[k][tm0 + 64];
            ulonglong2 wA = *(const ulonglong2*)&Bs[k][tn0];
            ulonglong2 wB = *(const ulonglong2*)&Bs[k][tn0 + 64];
            float ar[8] = {av0.x, av0.y, av0.z, av0.w, av1.x, av1.y, av1.z, av1.w};
#pragma unroll
            for (int i = 0; i < 8; i++) {
                u64 ai = pkdup(ar[i]);
                fma2(acc[i][0], ai, wA.x);
                fma2(acc[i][1], ai, wA.y);
                fma2(acc[i][2], ai, wB.x);
                fma2(acc[i][3], ai, wB.y);
            }
        }
        __syncthreads();
    }

    float bav[8];
#pragma unroll
    for (int j = 0; j < 4; j++) {
        bav[j]     = ba[h0 + tn0 + j];
        bav[4 + j] = ba[h0 + tn0 + 64 + j];
    }
#pragma unroll
    for (int gi = 0; gi < 2; gi++) {
#pragma unroll
        for (int ii = 0; ii < 4; ii++) {
            int i = gi * 4 + ii;
            int row = r0 + tm0 + gi * 64 + ii;
            float* o = g_xp + (size_t)row * HID + h0;
            float2 p0 = un2(acc[i][0]), p1 = un2(acc[i][1]);
            float2 p2 = un2(acc[i][2]), p3 = un2(acc[i][3]);
            *(float4*)(o + tn0)      = make_float4(p0.x + bav[0], p0.y + bav[1],
                                                   p1.x + bav[2], p1.y + bav[3]);
            *(float4*)(o + tn0 + 64) = make_float4(p2.x + bav[4], p2.y + bav[5],
                                                   p3.x + bav[6], p3.y + bav[7]);
        }
    }
}

// ---------------------------------------------------------------------------
// Kernel 2: persistent recurrence, ONE sync round per step (gather-tanh).
// CTA bi: h-tile ht=bi>>3 (64 h), k-slice ks=bi&7 (128 k), group g=ht>>1.
// Iter s (1..SEQ):
//   if s>1: wait cp[ks] >= 16(s-1)          [group-ks partials of step s-1]
//   gather: a_{s-1}[b][k0+k] = tanh(xp + sum_p partial[(s-1)%3][p][b][k0+k])
//           -> k-major smem (warp w owns b-octet w); the 2 CTAs with g==ks
//           also write their half of outs[s-1] (and hidden at s==SEQ).
//   release cd[ks]
//   if s<SEQ: compute partials^s (R11 f32x2 tile); per-warp wait
//           cd[g] >= 16(s-2) [2-step slack, off critical path]; STG to
//           buffer s%3; release cp[g].
// No phase2 round, no a_s store->load round-trip.
// ---------------------------------------------------------------------------
__global__ __launch_bounds__(256, 1) void rnn_persistent(
    const float* __restrict__ Waa, float* __restrict__ outs, int write_hidden)
{
    extern __shared__ float sm[];
    float* Ws = sm;                           // [128][64]

    const int tid = threadIdx.x;
    const int bi  = blockIdx.x;
    const int ht  = bi >> 3;                  // 0..15
    const int ks  = bi & 7;                   // 0..7
    const int g   = ht >> 1;                  // 0..7
    const int h0  = ht * 64;
    const int k0  = ks * 128;
    const int w   = tid >> 5;                 // warp = b-octet 0..7
    const int l   = tid & 31;

    float* Asw = sm + 128 * 64 + w * (128 * ASTRIDE);  // [128][12], cols 0..7 used

    unsigned* cp_own = g_sync + g * 64;
    unsigned* cp_ks  = g_sync + ks * 64;
    unsigned* cd_own = g_sync + 512 + g * 64;
    unsigned* cd_ks  = g_sync + 512 + ks * 64;

    // Load W_aa slice once: Ws[k][h] = Waa[h0+h][k0+k]
    {
        const int h  = tid & 63;
        const int kg = tid >> 6;
        const float* wrow = Waa + (size_t)(h0 + h) * HID + k0 + kg * 32;
#pragma unroll
        for (int j = 0; j < 8; j++) {
            float4 wv = *(const float4*)(wrow + j * 4);
            int k = kg * 32 + j * 4;
            Ws[(k + 0) * 64 + h] = wv.x; Ws[(k + 1) * 64 + h] = wv.y;
            Ws[(k + 2) * 64 + h] = wv.z; Ws[(k + 3) * 64 + h] = wv.w;
        }
    }
    __syncthreads();

    const int  hh = 2 * l;                    // compute h-pair within 64
    const bool wr = (g == ks);                // this CTA writes half of outs tile
    const int  wj = (ht & 1);                 // writer handles j-pair wj

    for (int s = 1; s <= SEQ; s++) {
        if (s > 1) {
            if (tid == 0) {
                const unsigned t = 16u * (unsigned)(s - 1);
                while (ldacq(cp_ks) < t) { }
            }
            __syncthreads();
        }

        // ---- gather-tanh: build a_{s-1}[8w..8w+8)[k0..k0+128) in Asw
        {
            const float* xpb = g_xp + (size_t)(s - 1) * BH;
            const float* pb  = g_partial[(s - 1) % 3];
#pragma unroll
            for (int j = 0; j < 4; j++) {
                const int k  = 32 * j + l;
                const int hg = k0 + k;
                float vals[8];
#pragma unroll
                for (int b = 0; b < 8; b++) {
                    const size_t off = (size_t)(8 * w + b) * HID + hg;
                    float v = __ldcg(xpb + off);
                    if (s > 1) {
#pragma unroll
                        for (int p = 0; p < KSLICES; p++)
                            v += __ldcg(pb + (size_t)p * BH + off);
                    }
                    vals[b] = tanhf(v);
                }
                *(float4*)(Asw + k * ASTRIDE)
                    = make_float4(vals[0], vals[1], vals[2], vals[3]);
                *(float4*)(Asw + k * ASTRIDE + 4)
                    = make_float4(vals[4], vals[5], vals[6], vals[7]);
                if (wr && (j >> 1) == wj) {
                    float* ob = outs + (size_t)(s - 1) * BH;
#pragma unroll
                    for (int b = 0; b < 8; b++) {
                        const size_t off = (size_t)(8 * w + b) * HID + hg;
                        ob[off] = vals[b];
                        if (write_hidden && s == SEQ) outs[SBH + off] = vals[b];
                    }
                }
            }
        }
        __syncthreads();                       // all partial/xp reads complete
        if (tid == 0) redrel(cd_ks);

        if (s < SEQ) {
            // ---- compute partials^s: acc[4 b-pairs][2 h] over 128 k
            u64 acc[4][2];
#pragma unroll
            for (int i = 0; i < 4; i++) { acc[i][0] = 0ull; acc[i][1] = 0ull; }

#pragma unroll 8
            for (int k = 0; k < 128; k++) {
                ulonglong2 aA = *(const ulonglong2*)(Asw + k * ASTRIDE);
                ulonglong2 aB = *(const ulonglong2*)(Asw + k * ASTRIDE + 4);
                float2 wv = *(const float2*)(Ws + k * 64 + hh);
                u64 w0 = pkdup(wv.x);
                u64 w1 = pkdup(wv.y);
                fma2(acc[0][0], aA.x, w0); fma2(acc[0][1], aA.x, w1);
                fma2(acc[1][0], aA.y, w0); fma2(acc[1][1], aA.y, w1);
                fma2(acc[2][0], aB.x, w0); fma2(acc[2][1], aB.x, w1);
                fma2(acc[3][0], aB.y, w0); fma2(acc[3][1], aB.y, w1);
            }

            // overwrite safety for buffer s%3 (holds partials^{s-3}, read at
            // iter s-2): 2-step slack, normally already satisfied
            if (l == 0 && s > 2) {
                const unsigned t = 16u * (unsigned)(s - 2);
                while (ldacq(cd_own) < t) { }
            }
            __syncwarp();

            float* gp = g_partial[s % 3] + (size_t)ks * BH
                      + (size_t)(8 * w) * HID + h0 + hh;
#pragma unroll
            for (int bp = 0; bp < 4; bp++) {
                float2 ev = un2(acc[bp][0]);
                float2 ov = un2(acc[bp][1]);
                *(float2*)(gp + (size_t)(2 * bp)     * HID) = make_float2(ev.x, ov.x);
                *(float2*)(gp + (size_t)(2 * bp + 1) * HID) = make_float2(ev.y, ov.y);
            }
            __syncthreads();                   // all warps' partials written
            if (tid == 0) redrel(cp_own);
        }
    }
}

// ---------------------------------------------------------------------------
// Launch. Inputs: X [B,S,E] f32, W_ax [H,E] f32, W_aa [H,H] f32, b_a [H] f32.
// Output: outputs [S,B,H] then hidden [B,H].
// ---------------------------------------------------------------------------
extern "C" void kernel_launch(void* const* d_in, const int* in_sizes, int n_in,
                              void* d_out, int out_size) {
    (void)in_sizes; (void)n_in;
    const float* X   = (const float*)d_in[0];
    const float* Wax = (const float*)d_in[1];
    const float* Waa = (const float*)d_in[2];
    const float* ba  = (const float*)d_in[3];
    float* out = (float*)d_out;

    cudaFuncSetAttribute(rnn_persistent,
                         cudaFuncAttributeMaxDynamicSharedMemorySize, RNN_SMEM);

    void* sp = nullptr;
    cudaGetSymbolAddress(&sp, g_sync);
    cudaMemsetAsync(sp, 0, 1024 * sizeof(unsigned), 0);

    dim3 g1((SEQ * BATCH) / 128, HID / 128);
    xproj_kernel<<<g1, 256>>>(X, Wax, ba);

    int write_hidden = (out_size >= (int)(SBH + BH)) ? 1 : 0;
    rnn_persistent<<<NBLOCKS, 256, RNN_SMEM>>>(Waa, out, write_hidden);
}

// round 16
// speedup vs baseline: 2.4295x; 1.4061x over previous
#include <cuda_runtime.h>
#include <math.h>

#define BATCH 64
#define SEQ   512
#define EMB   512
#define HID   1024
#define BH    (BATCH * HID)        // 65536
#define SBH   (SEQ * BH)           // 33554432
#define KSLICES 8
#define NBLOCKS 128                // 16 h-tiles (64h) x 8 k-slices (128k)

#define ASTRIDE 12                 // per-warp k-major staging row (floats)
#define PC (KSLICES * 32 * HID)    // partials per chain: 1 MB of floats
#define RNN_SMEM ((128 * 64 + 8 * 128 * ASTRIDE) * 4)   // 32KB Ws + 48KB Asw

typedef unsigned long long u64;

// W_aa K-split partials, per chain: [2][KSLICES][32][HID] = 2 MB
__device__ float g_partial[2 * PC];
// Counters: ca[c][g] at (c*8+g)*32, cp[c][g] at 512+(c*8+g)*32 (128B apart)
__device__ unsigned g_sync[1024];

// ---------------- packed fp32x2 helpers (sm_103a) ---------------------------
__device__ __forceinline__ u64 pkdup(float x) {
    u64 r; asm("mov.b64 %0, {%1, %1};" : "=l"(r) : "f"(x)); return r;
}
__device__ __forceinline__ void fma2(u64& d, u64 a, u64 b) {
    asm("fma.rn.f32x2 %0, %1, %2, %0;" : "+l"(d) : "l"(a), "l"(b));
}
__device__ __forceinline__ float2 un2(u64 v) {
    float2 f; asm("mov.b64 {%0, %1}, %2;" : "=f"(f.x), "=f"(f.y) : "l"(v));
    return f;
}
__device__ __forceinline__ unsigned ldacq(const unsigned* p) {
    unsigned v;
    asm volatile("ld.acquire.gpu.global.u32 %0, [%1];" : "=r"(v) : "l"(p));
    return v;
}
__device__ __forceinline__ void redrel(unsigned* p) {
    asm volatile("red.release.gpu.global.add.u32 [%0], %1;"
                 :: "l"(p), "r"(1u) : "memory");
}
// named barrier for one 128-thread half (ids 1 and 2)
__device__ __forceinline__ void hbar(int c) {
    asm volatile("bar.sync %0, 128;" :: "r"(c + 1) : "memory");
}

// ---------------------------------------------------------------------------
// Kernel 1: xproj[s][b][h] = sum_e X[b][s][e] * Wax[h][e] + ba[h]
// (unchanged R11 GEMM; writes into outs, consumed in place by the scan)
// ---------------------------------------------------------------------------
__global__ __launch_bounds__(256) void xproj_kernel(
    const float* __restrict__ X, const float* __restrict__ Wax,
    const float* __restrict__ ba, float* __restrict__ out)
{
    __shared__ float As[16][128];
    __shared__ float Bs[16][128];

    const int tid = threadIdx.x;
    const int r0 = blockIdx.x * 128;
    const int h0 = blockIdx.y * 128;

    const int lr = tid >> 1;
    const int lk = (tid & 1) * 8;
    const int r  = r0 + lr;
    const float* Aptr = X + (size_t)(r & (BATCH - 1)) * (SEQ * EMB)
                          + (size_t)(r >> 6) * EMB + lk;
    const float* Bptr = Wax + (size_t)(h0 + lr) * EMB + lk;

    const int tm0 = (tid >> 4) * 4;
    const int tn0 = (tid & 15) * 4;

    u64 acc[8][4];
#pragma unroll
    for (int i = 0; i < 8; i++)
#pragma unroll
        for (int p = 0; p < 4; p++) acc[i][p] = 0ull;

    for (int k0 = 0; k0 < EMB; k0 += 16) {
        float4 a0 = *(const float4*)(Aptr + k0);
        float4 a1 = *(const float4*)(Aptr + k0 + 4);
        float4 b0 = *(const float4*)(Bptr + k0);
        float4 b1 = *(const float4*)(Bptr + k0 + 4);
        As[lk + 0][lr] = a0.x; As[lk + 1][lr] = a0.y;
        As[lk + 2][lr] = a0.z; As[lk + 3][lr] = a0.w;
        As[lk + 4][lr] = a1.x; As[lk + 5][lr] = a1.y;
        As[lk + 6][lr] = a1.z; As[lk + 7][lr] = a1.w;
        Bs[lk + 0][lr] = b0.x; Bs[lk + 1][lr] = b0.y;
        Bs[lk + 2][lr] = b0.z; Bs[lk + 3][lr] = b0.w;
        Bs[lk + 4][lr] = b1.x; Bs[lk + 5][lr] = b1.y;
        Bs[lk + 6][lr] = b1.z; Bs[lk + 7][lr] = b1.w;
        __syncthreads();

#pragma unroll
        for (int k = 0; k < 16; k++) {
            float4 av0 = *(const float4*)&As[k][tm0];
            float4 av1 = *(const float4*)&As[k][tm0 + 64];
            ulonglong2 wA = *(const ulonglong2*)&Bs[k][tn0];
            ulonglong2 wB = *(const ulonglong2*)&Bs[k][tn0 + 64];
            float ar[8] = {av0.x, av0.y, av0.z, av0.w, av1.x, av1.y, av1.z, av1.w};
#pragma unroll
            for (int i = 0; i < 8; i++) {
                u64 ai = pkdup(ar[i]);
                fma2(acc[i][0], ai, wA.x);
                fma2(acc[i][1], ai, wA.y);
                fma2(acc[i][2], ai, wB.x);
                fma2(acc[i][3], ai, wB.y);
            }
        }
        __syncthreads();
    }

    float bav[8];
#pragma unroll
    for (int j = 0; j < 4; j++) {
        bav[j]     = ba[h0 + tn0 + j];
        bav[4 + j] = ba[h0 + tn0 + 64 + j];
    }
#pragma unroll
    for (int gi = 0; gi < 2; gi++) {
#pragma unroll
        for (int ii = 0; ii < 4; ii++) {
            int i = gi * 4 + ii;
            int row = r0 + tm0 + gi * 64 + ii;
            float* o = out + (size_t)row * HID + h0;
            float2 p0 = un2(acc[i][0]), p1 = un2(acc[i][1]);
            float2 p2 = un2(acc[i][2]), p3 = un2(acc[i][3]);
            *(float4*)(o + tn0)      = make_float4(p0.x + bav[0], p0.y + bav[1],
                                                   p1.x + bav[2], p1.y + bav[3]);
            *(float4*)(o + tn0 + 64) = make_float4(p2.x + bav[4], p2.y + bav[5],
                                                   p3.x + bav[6], p3.y + bav[7]);
        }
    }
}

// ---------------------------------------------------------------------------
// Kernel 2: persistent recurrence — R11 protocol, TWO chains on disjoint
// warp-halves. CTA bi: h-tile ht=bi>>3 (64 h), k-slice ks=bi&7 (128 k),
// group g=ht>>1. Half c (warps 4c..4c+3, named barrier id c+1) owns batch
// rows [32c, 32c+32) and runs an independent R11 step loop with counters
// ca[c][*], cp[c][*]. Warp wl=w&3 owns b-octet 32c+8wl; staging is
// warp-private ([128][12] k-major). W_aa smem tile shared read-only.
// ---------------------------------------------------------------------------
__global__ __launch_bounds__(256, 1) void rnn_persistent(
    const float* __restrict__ Waa, float* __restrict__ outs, int write_hidden)
{
    extern __shared__ float sm[];
    float* Ws = sm;                           // [128][64]

    const int tid = threadIdx.x;
    const int bi  = blockIdx.x;
    const int ht  = bi >> 3;                  // 0..15
    const int ks  = bi & 7;                   // 0..7
    const int g   = ht >> 1;                  // 0..7
    const int h0  = ht * 64;
    const int k0  = ks * 128;
    const int w   = tid >> 5;                 // global warp 0..7
    const int l   = tid & 31;
    const int c   = w >> 2;                   // chain 0/1
    const int wl  = w & 3;                    // b-octet within half
    const int tid2 = tid & 127;               // id within half

    float* Asw = sm + 128 * 64 + w * (128 * ASTRIDE);  // warp-private

    unsigned* ca_ks = g_sync + (c * 8 + ks) * 32;
    unsigned* ca_g  = g_sync + (c * 8 + g) * 32;
    unsigned* cp_g  = g_sync + 512 + (c * 8 + g) * 32;

    // Load W_aa slice once (CTA-wide): Ws[k][h] = Waa[h0+h][k0+k]
    {
        const int h  = tid & 63;
        const int kg = tid >> 6;
        const float* wrow = Waa + (size_t)(h0 + h) * HID + k0 + kg * 32;
#pragma unroll
        for (int j = 0; j < 8; j++) {
            float4 wv = *(const float4*)(wrow + j * 4);
            int k = kg * 32 + j * 4;
            Ws[(k + 0) * 64 + h] = wv.x; Ws[(k + 1) * 64 + h] = wv.y;
            Ws[(k + 2) * 64 + h] = wv.z; Ws[(k + 3) * 64 + h] = wv.w;
        }
    }
    __syncthreads();

    const int hh  = 2 * l;                    // h-pair within 64
    const int sbp = l & 7;                    // staging b within octet
    const int skb = (l >> 3) * 4;             // staging k base
    // phase2 map: e = cg*128 + tid2 -> (b = 32c + e>>6, h = 128g + 2*(e&63))
    const int cg = ((ht & 1) << 3) | ks;      // CTA index within group
    const int e  = cg * 128 + tid2;
    const size_t p2off = (size_t)(32 * c + (e >> 6)) * HID
                       + (size_t)g * 128 + 2 * (e & 63);
    const float* ppart = g_partial + (size_t)c * PC
                       + (size_t)(e >> 6) * HID + (size_t)g * 128 + 2 * (e & 63);

    for (int s = 0; s < SEQ; s++) {
        // prefetch own xproj element (only this thread ever writes it)
        float2 xp = *(const float2*)(outs + (size_t)s * BH + p2off);

        if (s > 0) {
            const unsigned t = 16u * (unsigned)s;
            if (tid2 == 0) {
                while (ldacq(ca_ks) < t) { }          // a_{s-1} k-slice ready
                if (g != ks) while (ldacq(ca_g) < t) { }  // partial overwrite safe
            }
            hbar(c);

            // ---- stage a_{s-1}[8 own rows][128 k] into warp-private smem
            const float* src = outs + (size_t)(s - 1) * BH
                             + (size_t)(32 * c + 8 * wl + sbp) * HID + k0 + skb;
#pragma unroll
            for (int j = 0; j < 8; j++) {
                float4 v = __ldcg((const float4*)(src + j * 16));
                int k = skb + j * 16;
                Asw[(k + 0) * ASTRIDE + sbp] = v.x;
                Asw[(k + 1) * ASTRIDE + sbp] = v.y;
                Asw[(k + 2) * ASTRIDE + sbp] = v.z;
                Asw[(k + 3) * ASTRIDE + sbp] = v.w;
            }
            __syncwarp();

            // ---- compute acc[4 b-pairs][2 h] over 128 k (R11 inner loop)
            u64 acc[4][2];
#pragma unroll
            for (int i = 0; i < 4; i++) { acc[i][0] = 0ull; acc[i][1] = 0ull; }

#pragma unroll 8
            for (int k = 0; k < 128; k++) {
                ulonglong2 aA = *(const ulonglong2*)(Asw + k * ASTRIDE);
                ulonglong2 aB = *(const ulonglong2*)(Asw + k * ASTRIDE + 4);
                float2 wv = *(const float2*)(Ws + k * 64 + hh);
                u64 w0 = pkdup(wv.x);
                u64 w1 = pkdup(wv.y);
                fma2(acc[0][0], aA.x, w0); fma2(acc[0][1], aA.x, w1);
                fma2(acc[1][0], aA.y, w0); fma2(acc[1][1], aA.y, w1);
                fma2(acc[2][0], aB.x, w0); fma2(acc[2][1], aB.x, w1);
                fma2(acc[3][0], aB.y, w0); fma2(acc[3][1], aB.y, w1);
            }

            // ---- write partials: g_partial[c][ks][8wl+row][h0+hh..+1]
            float* gp = g_partial + (size_t)c * PC + (size_t)ks * (32 * HID)
                      + (size_t)(8 * wl) * HID + h0 + hh;
#pragma unroll
            for (int bp = 0; bp < 4; bp++) {
                float2 ev = un2(acc[bp][0]);
                float2 ov = un2(acc[bp][1]);
                *(float2*)(gp + (size_t)(2 * bp)     * HID) = make_float2(ev.x, ov.x);
                *(float2*)(gp + (size_t)(2 * bp + 1) * HID) = make_float2(ev.y, ov.y);
            }
            hbar(c);                                   // all half's partials out
            if (tid2 == 0) {
                redrel(cp_g);
                while (ldacq(cp_g) < t) { }            // whole group's partials
            }
            hbar(c);
        }

        // ---- phase2: one float2 per thread, tanh(xp + sum8 partials)
        {
            float2 v = xp;
            if (s > 0) {
#pragma unroll
                for (int p = 0; p < KSLICES; p++) {
                    float2 q = __ldcg((const float2*)(ppart + (size_t)p * (32 * HID)));
                    v.x += q.x; v.y += q.y;
                }
            }
            v.x = tanhf(v.x); v.y = tanhf(v.y);
            *(float2*)(outs + (size_t)s * BH + p2off) = v;
            if (write_hidden && s == SEQ - 1)
                *(float2*)(outs + (size_t)SBH + p2off) = v;
        }
        hbar(c);                                       // half's a_s complete
        if (tid2 == 0) redrel(ca_g);
    }
}

// ---------------------------------------------------------------------------
// Launch. Inputs: X [B,S,E] f32, W_ax [H,E] f32, W_aa [H,H] f32, b_a [H] f32.
// Output: outputs [S,B,H] then hidden [B,H].
// ---------------------------------------------------------------------------
extern "C" void kernel_launch(void* const* d_in, const int* in_sizes, int n_in,
                              void* d_out, int out_size) {
    (void)in_sizes; (void)n_in;
    const float* X   = (const float*)d_in[0];
    const float* Wax = (const float*)d_in[1];
    const float* Waa = (const float*)d_in[2];
    const float* ba  = (const float*)d_in[3];
    float* out = (float*)d_out;

    cudaFuncSetAttribute(rnn_persistent,
                         cudaFuncAttributeMaxDynamicSharedMemorySize, RNN_SMEM);

    void* sp = nullptr;
    cudaGetSymbolAddress(&sp, g_sync);
    cudaMemsetAsync(sp, 0, 1024 * sizeof(unsigned), 0);

    dim3 g1((SEQ * BATCH) / 128, HID / 128);
    xproj_kernel<<<g1, 256>>>(X, Wax, ba, out);

    int write_hidden = (out_size >= (int)(SBH + BH)) ? 1 : 0;
    rnn_persistent<<<NBLOCKS, 256, RNN_SMEM>>>(Waa, out, write_hidden);
}